// round 3
// baseline (speedup 1.0000x reference)
#include <cuda_runtime.h>
#include <cuda_bf16.h>
#include <cstdint>

#define BATCH 16384
#define XD 784
#define ZD 64
#define KD 64
#define LOG2PI 1.8378770664093453

typedef unsigned long long ull;

// ---------------- device globals (scratch; no allocation allowed) ----------------
__device__ double g_D;                       // accumulates -0.5*SumSq - KL
__device__ float4 g_im[ZD * 32];             // [z*32+kk] = (i2[kk], mu*i2[kk], i2[kk+32], mu*i2[kk+32])
__device__ float  g_smu[KD];                 // sum_z mu^2 * i2
__device__ float  g_slog[KD];                // sum_z pz_y_logsigma
__device__ __nv_bfloat16 g_zb[BATCH * ZD];   // z in bf16 for decode GEMM
__device__ __nv_bfloat16 g_Wb[ZD * XD];      // W_dec in bf16

// ---------------- small helpers ----------------
__device__ __forceinline__ ull pack2(float x, float y) {
    ull r; asm("mov.b64 %0, {%1, %2};" : "=l"(r) : "f"(x), "f"(y)); return r;
}
__device__ __forceinline__ float2 unpk(ull v) {
    float2 f; asm("mov.b64 {%0, %1}, %2;" : "=f"(f.x), "=f"(f.y) : "l"(v)); return f;
}
__device__ __forceinline__ void ffma2(ull& d, ull a, ull b) {
    asm("fma.rn.f32x2 %0, %1, %2, %0;" : "+l"(d) : "l"(a), "l"(b));
}
__device__ __forceinline__ void ldsm_x4(uint32_t& r0, uint32_t& r1, uint32_t& r2, uint32_t& r3, uint32_t a) {
    asm volatile("ldmatrix.sync.aligned.m8n8.x4.shared.b16 {%0,%1,%2,%3}, [%4];"
                 : "=r"(r0), "=r"(r1), "=r"(r2), "=r"(r3) : "r"(a));
}
__device__ __forceinline__ void ldsm_x2t(uint32_t& r0, uint32_t& r1, uint32_t a) {
    asm volatile("ldmatrix.sync.aligned.m8n8.x2.trans.shared.b16 {%0,%1}, [%2];"
                 : "=r"(r0), "=r"(r1) : "r"(a));
}

// ---------------- kernel 1: precompute ----------------
// blocks 0..255   : z = qmu + exp(qls)*eps  -> g_zb (bf16), 4096 elems/block
// blocks 256..270 : W_dec -> g_Wb (bf16)
// block  271      : mixture matrix (i2, mu*i2), smu, slog, zero g_D
__global__ void __launch_bounds__(256) k_pre(
    const float* __restrict__ qmu, const float* __restrict__ qls,
    const float* __restrict__ eps, const float* __restrict__ W,
    const float* __restrict__ pmu, const float* __restrict__ pls)
{
    int bid = blockIdx.x, tid = threadIdx.x;
    if (bid < 256) {
        int i0 = bid * 4096 + tid * 16;
        #pragma unroll
        for (int u = 0; u < 4; ++u) {
            int i = i0 + u * 4;
            float4 m = *(const float4*)(qmu + i);
            float4 l = *(const float4*)(qls + i);
            float4 e = *(const float4*)(eps + i);
            float z0 = m.x + __expf(l.x) * e.x;
            float z1 = m.y + __expf(l.y) * e.y;
            float z2 = m.z + __expf(l.z) * e.z;
            float z3 = m.w + __expf(l.w) * e.w;
            __nv_bfloat162* dst = (__nv_bfloat162*)(g_zb + i);
            dst[0] = __floats2bfloat162_rn(z0, z1);
            dst[1] = __floats2bfloat162_rn(z2, z3);
        }
    } else if (bid < 271) {
        for (int i = (bid - 256) * 256 + tid; i < ZD * XD; i += 15 * 256)
            g_Wb[i] = __float2bfloat16_rn(W[i]);
    } else {
        for (int idx = tid; idx < ZD * 32; idx += 256) {
            int zi = idx >> 5, kk = idx & 31;
            float pl0 = pls[kk * ZD + zi],        mu0 = pmu[kk * ZD + zi];
            float pl1 = pls[(kk + 32) * ZD + zi], mu1 = pmu[(kk + 32) * ZD + zi];
            float i20 = 0.5f * __expf(-2.f * pl0);
            float i21 = 0.5f * __expf(-2.f * pl1);
            g_im[idx] = make_float4(i20, mu0 * i20, i21, mu1 * i21);
        }
        if (tid < KD) {
            float sm = 0.f, sl = 0.f;
            for (int z = 0; z < ZD; ++z) {
                float pl = pls[tid * ZD + z], mu = pmu[tid * ZD + z];
                sm = fmaf(mu * mu, 0.5f * __expf(-2.f * pl), sm);
                sl += pl;
            }
            g_smu[tid] = sm; g_slog[tid] = sl;
        }
        if (tid == 0) g_D = 0.0;
    }
}

// ---------------- kernel 2: mixture / KL ----------------
// 256 blocks x 256 threads; block handles 64 rows; warp handles 8 rows;
// lane <-> components (k=lane, k=lane+32). Packed f32x2 FMA accumulates (q1,q2).
__global__ void __launch_bounds__(256, 2) k_mix(
    const float* __restrict__ qmu, const float* __restrict__ qls,
    const float* __restrict__ eps, const float* __restrict__ pi)
{
    extern __shared__ char sm_raw[];
    float4* s_mat  = (float4*)sm_raw;                      // 2048 float4 = 32 KB
    float4* s_row  = (float4*)(sm_raw + 32768);            // 64 rows * 64 z   = 64 KB
    float*  s_sqls = (float*)(sm_raw + 32768 + 65536);     // 64
    float*  s_smu  = s_sqls + 64;                          // 64
    float*  s_slog = s_smu + 64;                           // 64

    int tid = threadIdx.x;
    int rb  = blockIdx.x * 64;

    for (int i = tid; i < ZD * 32; i += 256) s_mat[i] = g_im[i];
    if (tid < 64) { s_smu[tid] = g_smu[tid]; s_slog[tid] = g_slog[tid]; }

    // phase 1: row data (z^2, qmu^2+qs^2, -2z, -2qmu) into shared; sum(qls) per row
    {
        int r = tid >> 2, q = tid & 3;
        int gbase = (rb + r) * ZD + q * 16;
        float sq = 0.f;
        #pragma unroll
        for (int u = 0; u < 4; ++u) {
            float4 m = *(const float4*)(qmu + gbase + u * 4);
            float4 l = *(const float4*)(qls + gbase + u * 4);
            float4 e = *(const float4*)(eps + gbase + u * 4);
            float s0 = __expf(l.x), s1 = __expf(l.y), s2 = __expf(l.z), s3 = __expf(l.w);
            float z0 = m.x + s0 * e.x, z1 = m.y + s1 * e.y;
            float z2 = m.z + s2 * e.z, z3 = m.w + s3 * e.w;
            int zo = r * 64 + q * 16 + u * 4;
            s_row[zo + 0] = make_float4(z0 * z0, m.x * m.x + s0 * s0, -2.f * z0, -2.f * m.x);
            s_row[zo + 1] = make_float4(z1 * z1, m.y * m.y + s1 * s1, -2.f * z1, -2.f * m.y);
            s_row[zo + 2] = make_float4(z2 * z2, m.z * m.z + s2 * s2, -2.f * z2, -2.f * m.z);
            s_row[zo + 3] = make_float4(z3 * z3, m.w * m.w + s3 * s3, -2.f * z3, -2.f * m.w);
            sq += l.x + l.y + l.z + l.w;
        }
        sq += __shfl_xor_sync(0xffffffffu, sq, 1);
        sq += __shfl_xor_sync(0xffffffffu, sq, 2);
        if (q == 0) s_sqls[r] = sq;
    }
    __syncthreads();

    int w = tid >> 5, lane = tid & 31;
    int wrow = w * 8;
    ull accA[8], accB[8];
    #pragma unroll
    for (int r = 0; r < 8; ++r) { accA[r] = 0ull; accB[r] = 0ull; }

    // phase 2: packed bilinear forms. acc = (q1, q2) per (row, k)
    const ulonglong2* rp = (const ulonglong2*)s_row;
    #pragma unroll 2
    for (int z = 0; z < 64; ++z) {
        float4 mm = s_mat[z * 32 + lane];
        ull i2a = pack2(mm.x, mm.x), mua = pack2(mm.y, mm.y);
        ull i2b = pack2(mm.z, mm.z), mub = pack2(mm.w, mm.w);
        #pragma unroll
        for (int r = 0; r < 8; ++r) {
            ulonglong2 u = rp[(wrow + r) * 64 + z];   // (z2,w2) , (-2z,-2qmu)
            ffma2(accA[r], u.x, i2a);
            ffma2(accA[r], u.y, mua);
            ffma2(accB[r], u.x, i2b);
            ffma2(accB[r], u.y, mub);
        }
    }

    // phase 3: softmax + weighted KL per row
    float smua = s_smu[lane], smub = s_smu[lane + 32];
    float sla  = s_slog[lane], slb = s_slog[lane + 32];
    float wkl = 0.f;
    #pragma unroll
    for (int r = 0; r < 8; ++r) {
        int row = wrow + r;
        int b = rb + row;
        float2 A  = unpk(accA[r]);
        float2 Bv = unpk(accB[r]);
        float compa = -(A.x + smua) - sla;     // comp_lp (additive consts dropped; cancel in comp-lse)
        float compb = -(Bv.x + smub) - slb;
        float lpa = __logf(pi[b * 64 + lane]);
        float lpb = __logf(pi[b * 64 + lane + 32]);
        float pya = compa + lpa, pyb = compb + lpb;
        float mx = fmaxf(pya, pyb);
        #pragma unroll
        for (int o = 16; o; o >>= 1) mx = fmaxf(mx, __shfl_xor_sync(0xffffffffu, mx, o));
        float ea = __expf(pya - mx), eb = __expf(pyb - mx);
        float klva = sla + A.y + smua;         // klz k-dependent part
        float klvb = slb + Bv.y + smub;
        float s = ea + eb;
        float t = ea * (compa + klva) + eb * (compb + klvb);
        #pragma unroll
        for (int o = 16; o; o >>= 1) {
            s += __shfl_xor_sync(0xffffffffu, s, o);
            t += __shfl_xor_sync(0xffffffffu, t, o);
        }
        if (lane == 0) {
            float lse = mx + __logf(s);
            wkl += t / s - lse - s_sqls[row] - 32.f;  // + k-independent klz consts
        }
    }
    if (lane == 0) atomicAdd(&g_D, -(double)wkl);
}

// ---------------- kernel 3: decode sum-of-squares via bf16 tensor cores ----------------
// grid 1792 = 256 Mtiles(64 rows) x 7 Ntiles(112 cols); K=64 in 4 k16 steps.
__global__ void __launch_bounds__(256) k_dec(const float* __restrict__ x,
                                             const float* __restrict__ bdec)
{
    __shared__ alignas(16) __nv_bfloat16 sZ[64 * 72];    // padded stride 72 (conflict-free ldmatrix)
    __shared__ alignas(16) __nv_bfloat16 sW[64 * 120];   // padded stride 120
    __shared__ float sB[112];
    __shared__ float sred[8];

    int tid = threadIdx.x;
    int mt = blockIdx.x / 7, nt = blockIdx.x % 7;
    int mbase = mt * 64, nbase = nt * 112;

    {   // z tile: 64x64 bf16
        int r = tid >> 2, seg = tid & 3;
        const uint4* src = (const uint4*)(g_zb + (mbase + r) * 64 + seg * 16);
        uint4* dst = (uint4*)(sZ + r * 72 + seg * 16);
        dst[0] = src[0]; dst[1] = src[1];
    }
    for (int c = tid; c < 896; c += 256) {   // W tile: 64x112 bf16
        int r = c / 14, ch = c % 14;
        *(uint4*)(sW + r * 120 + ch * 8) = *(const uint4*)(g_Wb + r * 784 + nbase + ch * 8);
    }
    if (tid < 112) sB[tid] = bdec[nbase + tid];
    __syncthreads();

    int w = tid >> 5, lane = tid & 31;
    int mg = (w & 3) * 16, ng = (w >> 2) * 56;
    float c[7][4];
    #pragma unroll
    for (int j = 0; j < 7; ++j)
        #pragma unroll
        for (int i = 0; i < 4; ++i) c[j][i] = 0.f;

    #pragma unroll
    for (int kk = 0; kk < 64; kk += 16) {
        uint32_t a0, a1, a2, a3;
        uint32_t aaddr = (uint32_t)__cvta_generic_to_shared(
            &sZ[(mg + (lane & 15)) * 72 + kk + ((lane >> 4) << 3)]);
        ldsm_x4(a0, a1, a2, a3, aaddr);
        uint32_t bbase = (uint32_t)__cvta_generic_to_shared(
            &sW[(kk + (lane & 15)) * 120 + ng]);
        #pragma unroll
        for (int j = 0; j < 7; ++j) {
            uint32_t b0, b1;
            ldsm_x2t(b0, b1, bbase + j * 16);
            asm volatile("mma.sync.aligned.m16n8k16.row.col.f32.bf16.bf16.f32 "
                         "{%0,%1,%2,%3},{%4,%5,%6,%7},{%8,%9},{%0,%1,%2,%3};"
                         : "+f"(c[j][0]), "+f"(c[j][1]), "+f"(c[j][2]), "+f"(c[j][3])
                         : "r"(a0), "r"(a1), "r"(a2), "r"(a3), "r"(b0), "r"(b1));
        }
    }

    // epilogue: (x - (zW + b))^2, fused on C fragments
    int row0 = mbase + mg + (lane >> 2);
    float acc = 0.f;
    #pragma unroll
    for (int j = 0; j < 7; ++j) {
        int cl = ng + j * 8 + (lane & 3) * 2;
        int col = nbase + cl;
        float bb0 = sB[cl], bb1 = sB[cl + 1];
        float2 xa = *(const float2*)(x + (size_t)row0 * 784 + col);
        float d0 = xa.x - (c[j][0] + bb0);
        float d1 = xa.y - (c[j][1] + bb1);
        float2 xb = *(const float2*)(x + (size_t)(row0 + 8) * 784 + col);
        float d2 = xb.x - (c[j][2] + bb0);
        float d3 = xb.y - (c[j][3] + bb1);
        acc += d0 * d0 + d1 * d1 + d2 * d2 + d3 * d3;
    }
    #pragma unroll
    for (int o = 16; o; o >>= 1) acc += __shfl_xor_sync(0xffffffffu, acc, o);
    if (lane == 0) sred[w] = acc;
    __syncthreads();
    if (tid == 0) {
        float s = 0.f;
        #pragma unroll
        for (int i = 0; i < 8; ++i) s += sred[i];
        atomicAdd(&g_D, -0.5 * (double)s);
    }
}

// ---------------- kernel 4: finalize ----------------
__global__ void k_fin(float* out) {
    out[0] = (float)((g_D - 0.5 * LOG2PI * (double)BATCH * (double)XD) / (double)BATCH);
}

// ---------------- launch ----------------
extern "C" void kernel_launch(void* const* d_in, const int* in_sizes, int n_in,
                              void* d_out, int out_size) {
    const float* x    = (const float*)d_in[0];
    const float* pi   = (const float*)d_in[1];
    const float* qmu  = (const float*)d_in[2];
    const float* qls  = (const float*)d_in[3];
    const float* eps  = (const float*)d_in[4];
    const float* pmu  = (const float*)d_in[5];
    const float* pls  = (const float*)d_in[6];
    const float* W    = (const float*)d_in[7];
    const float* bdec = (const float*)d_in[8];

    cudaFuncSetAttribute(k_mix, cudaFuncAttributeMaxDynamicSharedMemorySize, 99072);

    k_pre<<<272, 256>>>(qmu, qls, eps, W, pmu, pls);
    k_mix<<<256, 256, 99072>>>(qmu, qls, eps, pi);
    k_dec<<<1792, 256>>>(x, bdec);
    k_fin<<<1, 1>>>((float*)d_out);
}